// round 15
// baseline (speedup 1.0000x reference)
#include <cuda_runtime.h>
#include <cuda_bf16.h>

// Problem: B=8, C=256, H=W=256.
//   h      = LeakyReLU(semantic @ W1^T + b1, 0.1)
//   logits = h @ W2^T + b2
//   w      = softmax(logits, axis=1)
//   out    = x * (1 + w[b,c])
//
// Structure:
//   K1 gate: ONE kernel, 128 blocks (single co-resident wave).
//       blocks 0..63  : layer 1 (wide), release via flag
//       blocks 64..127: prefetch W2 rows into REGISTERS while layer 1 runs,
//                       poll flag, then register-resident layer 2 + exp +
//                       deterministic partial sums. Last block resets flag.
//   K2 scale: frozen 86%-DRAM streamer with folded softmax denominator.

#define B_DIM 8
#define C_DIM 256
#define HW4 16384         // (256*256)/4 float4s per (b,c) plane
#define V_PER_THREAD 4
#define SCALE_THREADS 256
#define GATE_BLOCKS 128   // 64 layer-1 + 64 layer-2; < 148 => one wave

__device__ float g_h[B_DIM * C_DIM];      // hidden activations
__device__ float g_exp[B_DIM * C_DIM];    // exp(logits)
__device__ float g_psum[B_DIM * 8];       // per-block partial sums of exp
__device__ int   g_flag1 = 0;             // layer-1 completion count
__device__ int   g_done2 = 0;             // layer-2 completion count (for reset)

__global__ __launch_bounds__(256) void gate_kernel(
    const float* __restrict__ semantic,
    const float* __restrict__ W1,
    const float* __restrict__ b1,
    const float* __restrict__ W2,
    const float* __restrict__ b2)
{
    const int bid  = blockIdx.x;
    const int tid  = threadIdx.x;
    const int warp = tid >> 5;
    const int lane = tid & 31;

    __shared__ float s_vec[C_DIM];
    __shared__ float s_w[8];

    if (bid < 64) {
        // ================= Layer 1 (8 blocks per batch, 32 rows each) ======
        const int b    = bid >> 3;
        const int sub  = bid & 7;
        const int row0 = sub * 32 + warp * 4;

        s_vec[tid] = semantic[b * C_DIM + tid];
        __syncthreads();

        float acc[4] = {0.f, 0.f, 0.f, 0.f};
        #pragma unroll
        for (int i = 0; i < C_DIM / 32; ++i) {
            const int k = lane + i * 32;
            const float xin = s_vec[k];
            #pragma unroll
            for (int r = 0; r < 4; ++r)
                acc[r] = fmaf(xin, W1[(row0 + r) * C_DIM + k], acc[r]);
        }
        #pragma unroll
        for (int r = 0; r < 4; ++r) {
            float a = acc[r];
            #pragma unroll
            for (int s = 16; s > 0; s >>= 1)
                a += __shfl_xor_sync(0xFFFFFFFFu, a, s);
            if (lane == 0) {
                a += b1[row0 + r];
                __stcg(&g_h[b * C_DIM + row0 + r], (a > 0.f) ? a : 0.1f * a);
            }
        }
        __threadfence();
        __syncthreads();
        if (tid == 0) atomicAdd(&g_flag1, 1);
    }
    else {
        // ================= Layer 2 + exp + psum ============================
        const int a_   = bid - 64;
        const int b    = a_ >> 3;
        const int sub  = a_ & 7;
        const int row0 = sub * 32 + warp * 4;

        // ---- Prefetch W2 rows + biases into registers (independent of L1)
        float w[4][8];
        #pragma unroll
        for (int r = 0; r < 4; ++r)
            #pragma unroll
            for (int i = 0; i < 8; ++i)
                w[r][i] = W2[(row0 + r) * C_DIM + lane + i * 32];
        float bias[4];
        #pragma unroll
        for (int r = 0; r < 4; ++r) bias[r] = b2[row0 + r];

        // ---- Wait for layer 1 (protocol validated in R11)
        if (tid == 0) {
            while (*(volatile int*)&g_flag1 != 64) __nanosleep(32);
            __threadfence();
        }
        __syncthreads();

        s_vec[tid] = __ldcg(&g_h[b * C_DIM + tid]);
        __syncthreads();

        float acc[4] = {0.f, 0.f, 0.f, 0.f};
        #pragma unroll
        for (int i = 0; i < 8; ++i) {
            const float hin = s_vec[lane + i * 32];
            #pragma unroll
            for (int r = 0; r < 4; ++r)
                acc[r] = fmaf(hin, w[r][i], acc[r]);
        }

        float wsum = 0.0f;
        #pragma unroll
        for (int r = 0; r < 4; ++r) {
            float a = acc[r];
            #pragma unroll
            for (int s = 16; s > 0; s >>= 1)
                a += __shfl_xor_sync(0xFFFFFFFFu, a, s);
            if (lane == 0) {
                const float e = expf(a + bias[r]);       // no max-sub: |logit| small
                g_exp[b * C_DIM + row0 + r] = e;
                wsum += e;                                // fixed order
            }
        }
        if (lane == 0) s_w[warp] = wsum;
        __syncthreads();

        if (tid == 0) {
            float s = 0.0f;
            #pragma unroll
            for (int j = 0; j < 8; ++j) s += s_w[j];      // fixed order
            g_psum[a_] = s;

            // deterministic flag reset for graph replay
            const int d = atomicAdd(&g_done2, 1);
            if (d == 63) {
                g_flag1 = 0;
                __threadfence();
                g_done2 = 0;
                __threadfence();
            }
        }
    }
}

// ---------------------------------------------------------------------------
// Scale: g = 1 + e[bc] / sum_j psum[b*8+j]. Bulk path = measured 86%-DRAM.
// ---------------------------------------------------------------------------
__global__ __launch_bounds__(SCALE_THREADS) void scale_kernel(
    const float4* __restrict__ x,
    float4* __restrict__ out)
{
    const int bc = blockIdx.y;
    const int b  = bc >> 8;

    float denom = 0.0f;
    #pragma unroll
    for (int j = 0; j < 8; ++j) denom += g_psum[b * 8 + j];   // fixed order
    const float g = 1.0f + g_exp[bc] / denom;

    const long long base = (long long)bc * HW4
                         + (long long)blockIdx.x * (SCALE_THREADS * V_PER_THREAD)
                         + threadIdx.x;

    float4 v[V_PER_THREAD];
    #pragma unroll
    for (int i = 0; i < V_PER_THREAD; ++i)
        v[i] = x[base + i * SCALE_THREADS];

    #pragma unroll
    for (int i = 0; i < V_PER_THREAD; ++i) {
        v[i].x *= g; v[i].y *= g; v[i].z *= g; v[i].w *= g;
    }

    #pragma unroll
    for (int i = 0; i < V_PER_THREAD; ++i)
        out[base + i * SCALE_THREADS] = v[i];
}

extern "C" void kernel_launch(void* const* d_in, const int* in_sizes, int n_in,
                              void* d_out, int out_size)
{
    const float* x        = (const float*)d_in[0];
    const float* semantic = (const float*)d_in[1];
    const float* W1       = (const float*)d_in[2];
    const float* b1       = (const float*)d_in[3];
    const float* W2       = (const float*)d_in[4];
    const float* b2       = (const float*)d_in[5];
    float* out = (float*)d_out;

    gate_kernel<<<GATE_BLOCKS, 256>>>(semantic, W1, b1, W2, b2);

    dim3 grid(HW4 / (SCALE_THREADS * V_PER_THREAD), B_DIM * C_DIM);
    scale_kernel<<<grid, SCALE_THREADS>>>((const float4*)x, (float4*)out);
}